// round 17
// baseline (speedup 1.0000x reference)
#include <cuda_runtime.h>
#include <cuda_fp16.h>

#define NX    512
#define NPTS  32768
#define CCH   64
#define NB    4
#define PLANE (NX * NX)
#define BVOL  (PLANE * CCH)
#define NPTS_TOT (NB * NPTS)

// NHWC fp16 scratch (b, py, px, c). 134 MB.
__device__ __half g_xt[(size_t)NB * BVOL];
// Per-point records: 3x float4 weights (9 used) + 3x int4 offsets (9 used).
__device__ float4 g_rw[(size_t)NPTS_TOT * 3];
__device__ int4   g_ro[(size_t)NPTS_TOT * 3];

// ---------------------------------------------------------------------------
// Axis weights. Fast path (interior): weights sans exp(-2d^2) factor (cancels
// in normalization). Fallback (boundary, ~1% of points): exact clipped loop —
// its extra uniform per-axis factor also cancels in normalization.
// ---------------------------------------------------------------------------
__device__ __forceinline__ void axis_weights(float r, float pos, float w[3])
{
    if (r >= 2.0f && r <= 510.0f) {
        const float d  = r - pos;                 // in [-0.5, 0.5]
        const float U  = __expf( 1.5f * d);
        const float Ui = __expf(-1.5f * d);
        const float U2 = U * U,   U3 = U2 * U,   U4 = U2 * U2;
        const float V2 = Ui * Ui, V3 = V2 * Ui,  V4 = V2 * V2;
        const float C1 = 0.75484002f;             // exp(-0.28125)
        const float C2 = 0.32465246f;             // exp(-1.125)
        const float C3 = 0.07955951f;             // exp(-2.53125)
        const float C4 = 0.011108997f;            // exp(-4.5)
        w[0] = C4 * U4 + C3 * U3 + C2 * U2;       // m = 4,3,2
        w[1] = C1 * U  + 1.0f    + C1 * Ui;       // m = 1,0,-1
        w[2] = C2 * V2 + C3 * V3 + C4 * V4;       // m = -2,-3,-4
    } else {
        w[0] = w[1] = w[2] = 0.0f;
        #pragma unroll
        for (int j = 0; j < 9; j++) {
            const float o  = 1.5f - 0.375f * (float)j;          // off_n[j]
            const float p  = fminf(fmaxf(r - o, 0.f), 512.f);   // clip hi = nx (ref quirk)
            const float dd = p - pos;
            w[j / 3] += __expf(-2.f * dd * dd);
        }
    }
}

// ---------------------------------------------------------------------------
// Kernel 0: per-point records. 512 blocks x 256: every thread one point.
// ---------------------------------------------------------------------------
__global__ __launch_bounds__(256) void record_kernel(const float* __restrict__ coords)
{
    const int gp = blockIdx.x * 256 + threadIdx.x;
    const int b  = gp >> 15;
    const int n  = gp & (NPTS - 1);

    const float cy   = coords[((size_t)b * NPTS + n) * 2 + 0];
    const float cx   = coords[((size_t)b * NPTS + n) * 2 + 1];
    const float posx = cx * 511.0f;
    const float posy = cy * 511.0f;
    const float rx   = rintf(posx);               // jnp.round = half-to-even
    const float ry   = rintf(posy);

    float wx[3], wy[3];
    axis_weights(rx, posx, wx);
    axis_weights(ry, posy, wy);

    float w9[9];
    float s = 0.f;
    #pragma unroll
    for (int a = 0; a < 3; a++)
        #pragma unroll
        for (int c2 = 0; c2 < 3; c2++) {
            const float w = wx[a] * wy[c2];
            w9[a * 3 + c2] = w;
            s += w;
        }
    const float inv = 1.0f / s;

    const int irx = (int)rx;
    const int iry = (int)ry;
    int ixs[3], iys[3];
    #pragma unroll
    for (int a = 0; a < 3; a++) {
        ixs[a] = min(max(irx + 1 - a, 0), NX - 1);
        iys[a] = min(max(iry + 1 - a, 0), NX - 1);
    }

    int of[9];
    #pragma unroll
    for (int a = 0; a < 3; a++)
        #pragma unroll
        for (int c2 = 0; c2 < 3; c2++)
            of[a * 3 + c2] = (ixs[a] * NX + iys[c2]) * CCH;

    g_rw[3 * (size_t)gp + 0] = make_float4(w9[0] * inv, w9[1] * inv, w9[2] * inv, w9[3] * inv);
    g_rw[3 * (size_t)gp + 1] = make_float4(w9[4] * inv, w9[5] * inv, w9[6] * inv, w9[7] * inv);
    g_rw[3 * (size_t)gp + 2] = make_float4(w9[8] * inv, 0.f, 0.f, 0.f);
    g_ro[3 * (size_t)gp + 0] = make_int4(of[0], of[1], of[2], of[3]);
    g_ro[3 * (size_t)gp + 1] = make_int4(of[4], of[5], of[6], of[7]);
    g_ro[3 * (size_t)gp + 2] = make_int4(of[8], 0, 0, 0);
}

// ---------------------------------------------------------------------------
// Kernel 1: NCHW fp32 -> NHWC fp16 (round-10). Tile 64 px x 64 ch, 256 thr.
// ---------------------------------------------------------------------------
__global__ __launch_bounds__(256) void transpose_kernel(const float* __restrict__ x)
{
    __shared__ float s[64][65];               // [channel][pixel]

    const int tile = blockIdx.x;
    const int b    = tile >> 12;              // 4096 tiles per batch
    const int p0   = (tile & 4095) * 64;

    const int slot = threadIdx.x & 15;        // float4 slot (4 px)
    const int c0   = threadIdx.x >> 4;        // 0..15

    const float* xb = x + (size_t)b * BVOL;
    #pragma unroll
    for (int c = c0; c < 64; c += 16) {
        const float4 v = __ldcs((const float4*)(xb + (size_t)c * PLANE + p0 + slot * 4));
        s[c][slot * 4 + 0] = v.x;
        s[c][slot * 4 + 1] = v.y;
        s[c][slot * 4 + 2] = v.z;
        s[c][slot * 4 + 3] = v.w;
    }
    __syncthreads();

    __half* yb = g_xt + (size_t)b * BVOL + (size_t)p0 * CCH;
    #pragma unroll
    for (int i = threadIdx.x; i < 64 * 8; i += 256) {
        const int p   = i >> 3;               // pixel
        const int oct = i & 7;                // 8-channel octet
        __half2 h[4];
        #pragma unroll
        for (int j = 0; j < 4; j++)
            h[j] = __floats2half2_rn(s[oct * 8 + 2 * j][p], s[oct * 8 + 2 * j + 1][p]);
        *(int4*)(yb + (size_t)p * CCH + oct * 8) = *(const int4*)h;   // STG.128
    }
}

// ---------------------------------------------------------------------------
// Kernel 2: gather. Block = 256 threads, 32 consecutive points. No phase-1:
// records come from L2-hot g_rw/g_ro (broadcast LDG.128 across 16 lanes).
// Phase 2 = round-10 optimum (lane = channel quad, LDG.64 per tap).
// Phase 3 = round-10 scalar (c, n)-coalesced stores.
// ---------------------------------------------------------------------------
__global__ __launch_bounds__(256) void gather_kernel(float* __restrict__ out)
{
    __shared__ float s_out[64][33];           // [channel][point]

    const int p0g = blockIdx.x * 32;
    const int b   = p0g / NPTS;
    const int n0  = p0g % NPTS;
    const int tid = threadIdx.x;

    const int lane = tid & 31;
    const int warp = tid >> 5;
    const int cq   = lane & 15;               // channel quad (4 ch)
    const int sub  = lane >> 4;               // half-warp -> point select
    const __half* bp = g_xt + (size_t)b * BVOL + 4 * cq;

    #pragma unroll
    for (int it = 0; it < 2; it++) {
        const int p  = warp * 4 + it * 2 + sub;
        const size_t gp = (size_t)(p0g + p);

        const float4 wA = __ldg(&g_rw[3 * gp + 0]);
        const float4 wB = __ldg(&g_rw[3 * gp + 1]);
        const float4 wC = __ldg(&g_rw[3 * gp + 2]);
        const int4   oA = __ldg(&g_ro[3 * gp + 0]);
        const int4   oB = __ldg(&g_ro[3 * gp + 1]);
        const int4   oC = __ldg(&g_ro[3 * gp + 2]);

        const int   off[9] = {oA.x, oA.y, oA.z, oA.w, oB.x, oB.y, oB.z, oB.w, oC.x};
        const float w[9]   = {wA.x, wA.y, wA.z, wA.w, wB.x, wB.y, wB.z, wB.w, wC.x};

        int2 v[9];
        #pragma unroll
        for (int k = 0; k < 9; k++)
            v[k] = *(const int2*)(bp + off[k]);      // LDG.64, 4 channels

        float ax = 0.f, ay = 0.f, az = 0.f, aw = 0.f;
        #pragma unroll
        for (int k = 0; k < 9; k++) {
            const float2 f0 = __half22float2(*(const __half2*)&v[k].x);
            const float2 f1 = __half22float2(*(const __half2*)&v[k].y);
            ax += w[k] * f0.x;  ay += w[k] * f0.y;
            az += w[k] * f1.x;  aw += w[k] * f1.y;
        }
        s_out[4 * cq + 0][p] = ax;
        s_out[4 * cq + 1][p] = ay;
        s_out[4 * cq + 2][p] = az;
        s_out[4 * cq + 3][p] = aw;
    }
    __syncthreads();

    // ---- Phase 3: coalesced (c, n) scalar writes (round-10) ----
    float* ob = out + (size_t)b * CCH * NPTS + n0;
    #pragma unroll
    for (int i = tid; i < CCH * 32; i += 256) {
        const int j = i & 31;
        const int c = i >> 5;
        __stcs(ob + (size_t)c * NPTS + j, s_out[c][j]);
    }
}

extern "C" void kernel_launch(void* const* d_in, const int* in_sizes, int n_in,
                              void* d_out, int out_size) {
    const float* x      = (const float*)d_in[0];
    const float* coords = (const float*)d_in[1];
    if (n_in >= 2 && in_sizes[0] == NB * NPTS * 2) {   // defensive swap
        const float* t = x; x = coords; coords = t;
    }
    float* out = (float*)d_out;

    record_kernel<<<NPTS_TOT / 256, 256>>>(coords);
    transpose_kernel<<<NB * (PLANE / 64), 256>>>(x);
    gather_kernel<<<(NB * NPTS) / 32, 256>>>(out);
}